// round 6
// baseline (speedup 1.0000x reference)
#include <cuda_runtime.h>
#include <cuda_bf16.h>
#include <stdint.h>
#include <math.h>

#define Hd 1024
#define Sd 2048
#define Bd 16
#define Ad 8

#define BM 128            // CTA rows (2 warpgroups x 64)
#define BN 128            // N-tile
#define BKg 32            // K per chunk
#define STG 3             // stages per warpgroup
#define LDT 80            // padded row pitch bytes (32 bf16 data + pad)
#define A_SZ (64 * LDT)                 // 5120  (64 rows per WG)
#define B_SZ (128 * LDT)                // 10240
#define WG_STAGE (A_SZ + B_SZ)          // 15360
#define WG_BYTES (STG * WG_STAGE)       // 46080
#define SM_V    (2 * WG_BYTES)          // 92160
#define SM_C    (SM_V + 4096)           // 96256
#define SM_SRED (SM_C + 4096)           // 100352
#define SMEM_TOTAL (SM_SRED + 1024)     // 101376

// ---------------------------------------------------------------------------
__device__ __nv_bfloat16 g_Xbf[(size_t)Bd * Sd * Hd];  // 64 MB
__device__ __nv_bfloat16 g_Wt[(size_t)Hd * Hd];        // W1^T: [N][K]
__device__ float g_cvec[Bd * Hd];
__device__ float g_scores[Bd * Sd];
__device__ float g_weights[Bd * Sd];

// ---------------------------------------------------------------------------
__device__ __forceinline__ uint32_t smem_u32(const void* p) {
    uint32_t a;
    asm("{ .reg .u64 t; cvta.to.shared.u64 t, %1; cvt.u32.u64 %0, t; }" : "=r"(a) : "l"(p));
    return a;
}
__device__ __forceinline__ void cpa16(uint32_t dst, const void* src) {
    asm volatile("cp.async.cg.shared.global [%0], [%1], 16;" :: "r"(dst), "l"(src));
}
__device__ __forceinline__ void cpa_commit() {
    asm volatile("cp.async.commit_group;" ::: "memory");
}
#define CPA_WAIT1() asm volatile("cp.async.wait_group 1;" ::: "memory")
__device__ __forceinline__ void wg_bar(int id) {
    asm volatile("bar.sync %0, 128;" :: "r"(id) : "memory");
}
#define LDSM4(r, addr)                                                        \
    asm volatile("ldmatrix.sync.aligned.m8n8.x4.shared.b16 {%0,%1,%2,%3}, [%4];" \
        : "=r"((r)[0]), "=r"((r)[1]), "=r"((r)[2]), "=r"((r)[3]) : "r"(addr))
__device__ __forceinline__ void mma16816(float* d, const uint32_t* a,
                                         uint32_t b0, uint32_t b1) {
    asm volatile(
        "mma.sync.aligned.m16n8k16.row.col.f32.bf16.bf16.f32 "
        "{%0,%1,%2,%3}, {%4,%5,%6,%7}, {%8,%9}, {%0,%1,%2,%3};"
        : "+f"(d[0]), "+f"(d[1]), "+f"(d[2]), "+f"(d[3])
        : "r"(a[0]), "r"(a[1]), "r"(a[2]), "r"(a[3]), "r"(b0), "r"(b1));
}
__device__ __forceinline__ float fast_tanh(float x) {
    float y;
    asm("tanh.approx.f32 %0, %1;" : "=f"(y) : "f"(x));
    return y;
}

// ---------------------------------------------------------------------------
// Fused prep: blocks [0,4096) convert X; [4096,5120) transpose W1;
// [5120,5184) cvec.
// ---------------------------------------------------------------------------
__global__ void prep_kernel(const float4* __restrict__ X4,
                            const float* __restrict__ W,
                            const float* __restrict__ aspect,
                            const float* __restrict__ bias) {
    int bi = blockIdx.x, tid = threadIdx.x;
    if (bi < 4096) {
        int n4 = Bd * Sd * Hd / 4;
        for (int i = bi * 256 + tid; i < n4; i += 4096 * 256) {
            float4 v = X4[i];
            __nv_bfloat162 lo = __floats2bfloat162_rn(v.x, v.y);
            __nv_bfloat162 hi = __floats2bfloat162_rn(v.z, v.w);
            uint2 pk;
            pk.x = *reinterpret_cast<uint32_t*>(&lo);
            pk.y = *reinterpret_cast<uint32_t*>(&hi);
            reinterpret_cast<uint2*>(g_Xbf)[i] = pk;
        }
    } else if (bi < 5120) {
        __shared__ float t[32][33];
        int q = bi - 4096;
        int n0 = (q & 31) * 32, k0 = (q >> 5) * 32;
        int tx = tid & 31, ty = tid >> 5;            // 32 x 8
        #pragma unroll
        for (int i = 0; i < 32; i += 8)
            t[ty + i][tx] = W[(size_t)(k0 + ty + i) * Hd + n0 + tx];
        __syncthreads();
        #pragma unroll
        for (int i = 0; i < 32; i += 8)
            g_Wt[(size_t)(n0 + ty + i) * Hd + k0 + tx] = __float2bfloat16(t[tx][ty + i]);
    } else {
        __shared__ float asp[Hd];
        int q = bi - 5120;
        int b = q & 15, hb = q >> 4;
        for (int k = tid; k < Hd; k += 256) {
            float s = 0.f;
            #pragma unroll
            for (int a = 0; a < Ad; ++a)
                s += aspect[(size_t)(b * Ad + a) * Hd + k];
            asp[k] = s * (1.0f / Ad);
        }
        __syncthreads();
        int h = hb * 256 + tid;
        float acc = bias[h];
        const float* Wp = W + (size_t)Hd * Hd + h;
        #pragma unroll 8
        for (int k = 0; k < Hd; ++k)
            acc = fmaf(asp[k], Wp[(size_t)k * Hd], acc);
        g_cvec[b * Hd + h] = acc;
    }
}

// ---------------------------------------------------------------------------
// Fused GEMM + tanh + v-dot, two independent warpgroup pipelines per CTA.
// WG = 4 warps (2M x 2N), WG tile 64 x 128, warp tile 32 x 64.
// ---------------------------------------------------------------------------
__global__ void __launch_bounds__(256, 2)
gemm_score_mma(const float* __restrict__ v) {
    extern __shared__ char smem[];
    uint32_t sb = smem_u32(smem);
    float* v_s  = reinterpret_cast<float*>(smem + SM_V);
    float* c_s  = reinterpret_cast<float*>(smem + SM_C);
    float* sred = reinterpret_cast<float*>(smem + SM_SRED);

    int tid = threadIdx.x, lane = tid & 31, wid = tid >> 5;
    int wg = wid >> 2;                 // 0 or 1
    int wwid = wid & 3;                // warp within WG
    int wtid = tid & 127;              // thread within WG
    int warpM = wwid & 1, warpN = wwid >> 1;
    int m0 = blockIdx.x * BM;
    int b = m0 >> 11;

    for (int i = tid; i < Hd; i += 256) {
        v_s[i] = v[i];
        c_s[i] = g_cvec[b * Hd + i];
    }
    __syncthreads();

    uint32_t wgbase = sb + wg * WG_BYTES;

    // ldmatrix offsets (within a WG stage)
    uint32_t aoff[2], boff[4];
    #pragma unroll
    for (int mt = 0; mt < 2; ++mt) {
        int r = warpM * 32 + mt * 16 + ((lane >> 3) & 1) * 8 + (lane & 7);
        aoff[mt] = r * LDT + (lane >> 4) * 16;
    }
    #pragma unroll
    for (int jp = 0; jp < 4; ++jp) {
        int n = warpN * 64 + (jp * 2 + (lane >> 4)) * 8 + (lane & 7);
        boff[jp] = A_SZ + n * LDT + ((lane >> 3) & 1) * 16;
    }

    const __nv_bfloat16* Ag = g_Xbf + (size_t)(m0 + wg * 64) * Hd;
    const __nv_bfloat16* Bg = g_Wt;

    // cp.async mapping within WG (128 threads):
    // A: 64 rows x 64B -> 2 chunks/thread; B: 128 rows x 64B -> 4 chunks/thread
    int arow = wtid >> 1;
    int acb  = (wtid & 1) * 32;        // byte col (2 x 16B)
    int ack  = (wtid & 1) * 16;        // element col

    float acc[2][8][4];
    #pragma unroll
    for (int mt = 0; mt < 2; ++mt)
        #pragma unroll
        for (int j = 0; j < 8; ++j)
            #pragma unroll
            for (int e = 0; e < 4; ++e) acc[mt][j][e] = 0.f;
    float p[4] = {0.f, 0.f, 0.f, 0.f};

    const int G = 8 * 32;

    // prologue: stages 0,1
    #pragma unroll
    for (int q = 0; q < STG - 1; ++q) {
        int n0 = (q >> 5) * BN, k0 = (q & 31) * BKg;
        uint32_t base = wgbase + q * WG_STAGE;
        cpa16(base + arow * LDT + acb,      Ag + (size_t)arow * Hd + k0 + ack);
        cpa16(base + arow * LDT + acb + 16, Ag + (size_t)arow * Hd + k0 + ack + 8);
        uint32_t bb = base + A_SZ + wtid * LDT;
        const __nv_bfloat16* bgr = Bg + (size_t)(n0 + wtid) * Hd + k0;
        #pragma unroll
        for (int c = 0; c < 4; ++c) cpa16(bb + c * 16, bgr + c * 8);
        cpa_commit();
    }

    int stg = STG - 1;    // stage slot for next issue
    int cur = 0;          // stage slot being computed
    for (int g = 0; g < G; ++g) {
        CPA_WAIT1();          // this thread's group g done
        wg_bar(wg + 1);       // publish WG's copies; fences reuse of slot stg
        int q = g + STG - 1;
        if (q < G) {
            int n0 = (q >> 5) * BN, k0 = (q & 31) * BKg;
            uint32_t base = wgbase + stg * WG_STAGE;
            cpa16(base + arow * LDT + acb,      Ag + (size_t)arow * Hd + k0 + ack);
            cpa16(base + arow * LDT + acb + 16, Ag + (size_t)arow * Hd + k0 + ack + 8);
            uint32_t bb = base + A_SZ + wtid * LDT;
            const __nv_bfloat16* bgr = Bg + (size_t)(n0 + wtid) * Hd + k0;
            #pragma unroll
            for (int c = 0; c < 4; ++c) cpa16(bb + c * 16, bgr + c * 8);
        }
        cpa_commit();         // unconditional: keeps wait accounting exact
        if (++stg == STG) stg = 0;

        uint32_t ab = wgbase + cur * WG_STAGE;
        if (++cur == STG) cur = 0;

        // staggered ks0/ks1
        uint32_t a0[2][4], b0[4][4], a1[2][4], b1[4][4];
        LDSM4(a0[0], ab + aoff[0]);
        LDSM4(a0[1], ab + aoff[1]);
        #pragma unroll
        for (int jp = 0; jp < 4; ++jp) LDSM4(b0[jp], ab + boff[jp]);
        LDSM4(a1[0], ab + aoff[0] + 32);
        LDSM4(a1[1], ab + aoff[1] + 32);

        #pragma unroll
        for (int mt = 0; mt < 2; ++mt)
            #pragma unroll
            for (int j = 0; j < 8; ++j)
                mma16816(acc[mt][j], a0[mt], b0[j >> 1][(j & 1) * 2],
                         b0[j >> 1][(j & 1) * 2 + 1]);

        #pragma unroll
        for (int jp = 0; jp < 4; ++jp) LDSM4(b1[jp], ab + boff[jp] + 32);

        #pragma unroll
        for (int mt = 0; mt < 2; ++mt)
            #pragma unroll
            for (int j = 0; j < 8; ++j)
                mma16816(acc[mt][j], a1[mt], b1[j >> 1][(j & 1) * 2],
                         b1[j >> 1][(j & 1) * 2 + 1]);

        if ((g & 31) == 31) {
            int nt = g >> 5;
            int nb = nt * BN + warpN * 64 + (lane & 3) * 2;
            #pragma unroll
            for (int mt = 0; mt < 2; ++mt)
                #pragma unroll
                for (int j = 0; j < 8; ++j) {
                    int n0e = nb + j * 8;
                    #pragma unroll
                    for (int e = 0; e < 4; ++e) {
                        int n = n0e + (e & 1);
                        float x = acc[mt][j][e] + c_s[n];
                        p[mt * 2 + (e >> 1)] += v_s[n] * fast_tanh(x);
                        acc[mt][j][e] = 0.f;
                    }
                }
        }
    }

    #pragma unroll
    for (int i = 0; i < 4; ++i) {
        p[i] += __shfl_xor_sync(0xFFFFFFFFu, p[i], 1);
        p[i] += __shfl_xor_sync(0xFFFFFFFFu, p[i], 2);
    }
    if ((lane & 3) == 0) {
        #pragma unroll
        for (int mt = 0; mt < 2; ++mt)
            #pragma unroll
            for (int rh = 0; rh < 2; ++rh) {
                int row = wg * 64 + warpM * 32 + mt * 16 + (lane >> 2) + rh * 8;
                sred[row * 2 + warpN] = p[mt * 2 + rh];
            }
    }
    __syncthreads();
    if (tid < BM)
        g_scores[m0 + tid] = sred[tid * 2] + sred[tid * 2 + 1];
}

// ---------------------------------------------------------------------------
__global__ void softmax_kernel() {
    int b = blockIdx.x, tid = threadIdx.x;
    __shared__ float red[256];
    float m = -1e30f;
    for (int s = tid; s < Sd; s += 256)
        m = fmaxf(m, g_scores[b * Sd + s]);
    red[tid] = m;
    __syncthreads();
    for (int o = 128; o > 0; o >>= 1) {
        if (tid < o) red[tid] = fmaxf(red[tid], red[tid + o]);
        __syncthreads();
    }
    float mx = red[0];
    __syncthreads();
    float sum = 0.f;
    for (int s = tid; s < Sd; s += 256) {
        float e = expf(g_scores[b * Sd + s] - mx);
        g_weights[b * Sd + s] = e;
        sum += e;
    }
    red[tid] = sum;
    __syncthreads();
    for (int o = 128; o > 0; o >>= 1) {
        if (tid < o) red[tid] += red[tid + o];
        __syncthreads();
    }
    float inv = 1.0f / red[0];
    for (int s = tid; s < Sd; s += 256)
        g_weights[b * Sd + s] *= inv;
}

__global__ void scale_kernel(const float* __restrict__ X, float* __restrict__ out,
                             int total4) {
    int idx = blockIdx.x * blockDim.x + threadIdx.x;
    int stride = gridDim.x * blockDim.x;
    for (int i = idx; i < total4; i += stride) {
        float w = 1.0f + g_weights[i >> 8];
        float4 t = ((const float4*)X)[i];
        t.x *= w; t.y *= w; t.z *= w; t.w *= w;
        ((float4*)out)[i] = t;
    }
}

// ---------------------------------------------------------------------------
extern "C" void kernel_launch(void* const* d_in, const int* in_sizes, int n_in,
                              void* d_out, int out_size) {
    const float* tok  = (const float*)d_in[0];
    const float* asp  = (const float*)d_in[1];
    const float* W    = (const float*)d_in[2];
    const float* bias = (const float*)d_in[3];
    const float* v    = (const float*)d_in[4];
    float* out = (float*)d_out;

    cudaFuncSetAttribute(gemm_score_mma, cudaFuncAttributeMaxDynamicSharedMemorySize,
                         SMEM_TOTAL);

    prep_kernel<<<5184, 256>>>((const float4*)tok, W, asp, bias);
    gemm_score_mma<<<(Bd * Sd) / BM, 256, SMEM_TOTAL>>>(v);
    softmax_kernel<<<Bd, 256>>>();
    scale_kernel<<<8192, 256>>>(tok, out, (Bd * Sd * Hd) / 4);
}

// round 7
// speedup vs baseline: 1.1103x; 1.1103x over previous
#include <cuda_runtime.h>
#include <cuda_bf16.h>
#include <stdint.h>
#include <math.h>

#define Hd 1024
#define Sd 2048
#define Bd 16
#define Ad 8

#define BM 128
#define BN 128
#define BKg 64                          // K per chunk (64 MMAs per sync)
#define LDT 144                         // row pitch bytes: 128B data + 16B pad
#define A_SZ (BM * LDT)                 // 18432
#define STAGE_BYTES (2 * A_SZ)          // 36864 (A + B)
#define STG 2
#define SM_V    (STG * STAGE_BYTES)     // 73728
#define SM_C    (SM_V + 4096)           // 77824
#define SM_SRED (SM_C + 4096)           // 81920
#define SMEM_TOTAL (SM_SRED + 1024)     // 82944  (x2 CTAs = 166KB/SM)

// ---------------------------------------------------------------------------
__device__ __nv_bfloat16 g_Xbf[(size_t)Bd * Sd * Hd];  // 64 MB
__device__ __nv_bfloat16 g_Wt[(size_t)Hd * Hd];        // W1^T: [N][K]
__device__ float g_cvec[Bd * Hd];
__device__ float g_scores[Bd * Sd];
__device__ float g_weights[Bd * Sd];

// ---------------------------------------------------------------------------
__device__ __forceinline__ uint32_t smem_u32(const void* p) {
    uint32_t a;
    asm("{ .reg .u64 t; cvta.to.shared.u64 t, %1; cvt.u32.u64 %0, t; }" : "=r"(a) : "l"(p));
    return a;
}
__device__ __forceinline__ void cpa16(uint32_t dst, const void* src) {
    asm volatile("cp.async.cg.shared.global [%0], [%1], 16;" :: "r"(dst), "l"(src));
}
__device__ __forceinline__ void cpa_commit() {
    asm volatile("cp.async.commit_group;" ::: "memory");
}
#define CPA_WAIT0() asm volatile("cp.async.wait_group 0;" ::: "memory")
#define LDSM4(r, addr)                                                        \
    asm volatile("ldmatrix.sync.aligned.m8n8.x4.shared.b16 {%0,%1,%2,%3}, [%4];" \
        : "=r"((r)[0]), "=r"((r)[1]), "=r"((r)[2]), "=r"((r)[3]) : "r"(addr))
__device__ __forceinline__ void mma16816(float* d, const uint32_t* a,
                                         uint32_t b0, uint32_t b1) {
    asm volatile(
        "mma.sync.aligned.m16n8k16.row.col.f32.bf16.bf16.f32 "
        "{%0,%1,%2,%3}, {%4,%5,%6,%7}, {%8,%9}, {%0,%1,%2,%3};"
        : "+f"(d[0]), "+f"(d[1]), "+f"(d[2]), "+f"(d[3])
        : "r"(a[0]), "r"(a[1]), "r"(a[2]), "r"(a[3]), "r"(b0), "r"(b1));
}
__device__ __forceinline__ float fast_tanh(float x) {
    float y;
    asm("tanh.approx.f32 %0, %1;" : "=f"(y) : "f"(x));
    return y;
}

// ---------------------------------------------------------------------------
// Fused prep: blocks [0,4096) convert X; [4096,5120) transpose W1;
// [5120,5184) cvec.
// ---------------------------------------------------------------------------
__global__ void prep_kernel(const float4* __restrict__ X4,
                            const float* __restrict__ W,
                            const float* __restrict__ aspect,
                            const float* __restrict__ bias) {
    int bi = blockIdx.x, tid = threadIdx.x;
    if (bi < 4096) {
        int n4 = Bd * Sd * Hd / 4;
        for (int i = bi * 256 + tid; i < n4; i += 4096 * 256) {
            float4 v = X4[i];
            __nv_bfloat162 lo = __floats2bfloat162_rn(v.x, v.y);
            __nv_bfloat162 hi = __floats2bfloat162_rn(v.z, v.w);
            uint2 pk;
            pk.x = *reinterpret_cast<uint32_t*>(&lo);
            pk.y = *reinterpret_cast<uint32_t*>(&hi);
            reinterpret_cast<uint2*>(g_Xbf)[i] = pk;
        }
    } else if (bi < 5120) {
        __shared__ float t[32][33];
        int q = bi - 4096;
        int n0 = (q & 31) * 32, k0 = (q >> 5) * 32;
        int tx = tid & 31, ty = tid >> 5;            // 32 x 8
        #pragma unroll
        for (int i = 0; i < 32; i += 8)
            t[ty + i][tx] = W[(size_t)(k0 + ty + i) * Hd + n0 + tx];
        __syncthreads();
        #pragma unroll
        for (int i = 0; i < 32; i += 8)
            g_Wt[(size_t)(n0 + ty + i) * Hd + k0 + tx] = __float2bfloat16(t[tx][ty + i]);
    } else {
        __shared__ float asp[Hd];
        int q = bi - 5120;
        int b = q & 15, hb = q >> 4;
        for (int k = tid; k < Hd; k += 256) {
            float s = 0.f;
            #pragma unroll
            for (int a = 0; a < Ad; ++a)
                s += aspect[(size_t)(b * Ad + a) * Hd + k];
            asp[k] = s * (1.0f / Ad);
        }
        __syncthreads();
        int h = hb * 256 + tid;
        float acc = bias[h];
        const float* Wp = W + (size_t)Hd * Hd + h;
        #pragma unroll 8
        for (int k = 0; k < Hd; ++k)
            acc = fmaf(asp[k], Wp[(size_t)k * Hd], acc);
        g_cvec[b * Hd + h] = acc;
    }
}

// ---------------------------------------------------------------------------
// Fused GEMM + tanh + v-dot. 8 warps, warp grid 4(M) x 2(N), warp tile 32x64.
// K chunk = 64 (64 MMAs per warp per sync point); double-buffered.
// Per iter: wait(0) -> bar(publish) -> issue next chunk -> compute.
// ---------------------------------------------------------------------------
__global__ void __launch_bounds__(256, 2)
gemm_score_mma(const float* __restrict__ v) {
    extern __shared__ char smem[];
    uint32_t sb = smem_u32(smem);
    float* v_s  = reinterpret_cast<float*>(smem + SM_V);
    float* c_s  = reinterpret_cast<float*>(smem + SM_C);
    float* sred = reinterpret_cast<float*>(smem + SM_SRED);

    int tid = threadIdx.x, lane = tid & 31, wid = tid >> 5;
    int warpM = wid & 3, warpN = wid >> 2;
    int m0 = blockIdx.x * BM;
    int b = m0 >> 11;

    // ldmatrix per-thread offsets (within a stage)
    uint32_t aoff[2], boff[4];
    #pragma unroll
    for (int mt = 0; mt < 2; ++mt) {
        int r = warpM * 32 + mt * 16 + ((lane >> 3) & 1) * 8 + (lane & 7);
        aoff[mt] = r * LDT + (lane >> 4) * 16;
    }
    #pragma unroll
    for (int jp = 0; jp < 4; ++jp) {
        int n = warpN * 64 + (jp * 2 + (lane >> 4)) * 8 + (lane & 7);
        boff[jp] = A_SZ + n * LDT + ((lane >> 3) & 1) * 16;
    }

    const __nv_bfloat16* Ag = g_Xbf + (size_t)m0 * Hd;
    const __nv_bfloat16* Bg = g_Wt;

    // cp.async mapping: A/B each 128 rows x 128B -> 1024 chunks; 4/thread each
    int arow = tid >> 1;
    int acb  = (tid & 1) * 64;      // byte offset within row
    int ack  = (tid & 1) * 32;      // element offset

    float acc[2][8][4];
    #pragma unroll
    for (int mt = 0; mt < 2; ++mt)
        #pragma unroll
        for (int j = 0; j < 8; ++j)
            #pragma unroll
            for (int e = 0; e < 4; ++e) acc[mt][j][e] = 0.f;
    float p[4] = {0.f, 0.f, 0.f, 0.f};

    const int G = 8 * 16;           // 8 N-tiles x 16 K-chunks

    // prologue: issue chunk 0 into stage 0
    {
        uint32_t base = sb;
        const __nv_bfloat16* ar = Ag + (size_t)arow * Hd + ack;
        const __nv_bfloat16* br = Bg + (size_t)arow * Hd + ack;
        #pragma unroll
        for (int c = 0; c < 4; ++c) {
            cpa16(base + arow * LDT + acb + c * 16,        ar + c * 8);
            cpa16(base + A_SZ + arow * LDT + acb + c * 16, br + c * 8);
        }
        cpa_commit();
    }
    for (int i = tid; i < Hd; i += 256) {
        v_s[i] = v[i];
        c_s[i] = g_cvec[b * Hd + i];
    }

    for (int g = 0; g < G; ++g) {
        int s = g & 1;
        CPA_WAIT0();        // this thread's chunk-g copies done
        __syncthreads();    // publish all threads' copies; all threads are
                            // also done computing stage s^1 (iter g-1)

        int q = g + 1;
        if (q < G) {
            int n0 = (q >> 4) * BN, k0 = (q & 15) * BKg;
            uint32_t base = sb + (s ^ 1) * STAGE_BYTES;
            const __nv_bfloat16* ar = Ag + (size_t)arow * Hd + k0 + ack;
            const __nv_bfloat16* br = Bg + (size_t)(n0 + arow) * Hd + k0 + ack;
            #pragma unroll
            for (int c = 0; c < 4; ++c) {
                cpa16(base + arow * LDT + acb + c * 16,        ar + c * 8);
                cpa16(base + A_SZ + arow * LDT + acb + c * 16, br + c * 8);
            }
            cpa_commit();
        }

        uint32_t ab = sb + s * STAGE_BYTES;

        // 4 k-steps, staggered in pairs: ks MMAs cover ks+1's LDSM latency
        #pragma unroll
        for (int kp = 0; kp < 2; ++kp) {
            uint32_t koff0 = (2 * kp) * 32, koff1 = (2 * kp + 1) * 32;
            uint32_t a0[2][4], b0[4][4], a1[2][4], b1[4][4];
            LDSM4(a0[0], ab + aoff[0] + koff0);
            LDSM4(a0[1], ab + aoff[1] + koff0);
            #pragma unroll
            for (int jp = 0; jp < 4; ++jp) LDSM4(b0[jp], ab + boff[jp] + koff0);
            LDSM4(a1[0], ab + aoff[0] + koff1);
            LDSM4(a1[1], ab + aoff[1] + koff1);

            #pragma unroll
            for (int mt = 0; mt < 2; ++mt)
                #pragma unroll
                for (int j = 0; j < 8; ++j)
                    mma16816(acc[mt][j], a0[mt], b0[j >> 1][(j & 1) * 2],
                             b0[j >> 1][(j & 1) * 2 + 1]);

            #pragma unroll
            for (int jp = 0; jp < 4; ++jp) LDSM4(b1[jp], ab + boff[jp] + koff1);

            #pragma unroll
            for (int mt = 0; mt < 2; ++mt)
                #pragma unroll
                for (int j = 0; j < 8; ++j)
                    mma16816(acc[mt][j], a1[mt], b1[j >> 1][(j & 1) * 2],
                             b1[j >> 1][(j & 1) * 2 + 1]);
        }

        if ((g & 15) == 15) {
            int nt = g >> 4;
            int nb = nt * BN + warpN * 64 + (lane & 3) * 2;
            #pragma unroll
            for (int mt = 0; mt < 2; ++mt)
                #pragma unroll
                for (int j = 0; j < 8; ++j) {
                    int n0e = nb + j * 8;
                    #pragma unroll
                    for (int e = 0; e < 4; ++e) {
                        int n = n0e + (e & 1);
                        float x = acc[mt][j][e] + c_s[n];
                        p[mt * 2 + (e >> 1)] += v_s[n] * fast_tanh(x);
                        acc[mt][j][e] = 0.f;
                    }
                }
        }
    }

    #pragma unroll
    for (int i = 0; i < 4; ++i) {
        p[i] += __shfl_xor_sync(0xFFFFFFFFu, p[i], 1);
        p[i] += __shfl_xor_sync(0xFFFFFFFFu, p[i], 2);
    }
    if ((lane & 3) == 0) {
        #pragma unroll
        for (int mt = 0; mt < 2; ++mt)
            #pragma unroll
            for (int rh = 0; rh < 2; ++rh) {
                int row = warpM * 32 + mt * 16 + (lane >> 2) + rh * 8;
                sred[row * 2 + warpN] = p[mt * 2 + rh];
            }
    }
    __syncthreads();
    if (tid < BM)
        g_scores[m0 + tid] = sred[tid * 2] + sred[tid * 2 + 1];
}

// ---------------------------------------------------------------------------
__global__ void softmax_kernel() {
    int b = blockIdx.x, tid = threadIdx.x;
    __shared__ float red[256];
    float m = -1e30f;
    for (int s = tid; s < Sd; s += 256)
        m = fmaxf(m, g_scores[b * Sd + s]);
    red[tid] = m;
    __syncthreads();
    for (int o = 128; o > 0; o >>= 1) {
        if (tid < o) red[tid] = fmaxf(red[tid], red[tid + o]);
        __syncthreads();
    }
    float mx = red[0];
    __syncthreads();
    float sum = 0.f;
    for (int s = tid; s < Sd; s += 256) {
        float e = expf(g_scores[b * Sd + s] - mx);
        g_weights[b * Sd + s] = e;
        sum += e;
    }
    red[tid] = sum;
    __syncthreads();
    for (int o = 128; o > 0; o >>= 1) {
        if (tid < o) red[tid] += red[tid + o];
        __syncthreads();
    }
    float inv = 1.0f / red[0];
    for (int s = tid; s < Sd; s += 256)
        g_weights[b * Sd + s] *= inv;
}

__global__ void scale_kernel(const float* __restrict__ X, float* __restrict__ out,
                             int total4) {
    int idx = blockIdx.x * blockDim.x + threadIdx.x;
    int stride = gridDim.x * blockDim.x;
    for (int i = idx; i < total4; i += stride) {
        float w = 1.0f + g_weights[i >> 8];
        float4 t = ((const float4*)X)[i];
        t.x *= w; t.y *= w; t.z *= w; t.w *= w;
        ((float4*)out)[i] = t;
    }
}

// ---------------------------------------------------------------------------
extern "C" void kernel_launch(void* const* d_in, const int* in_sizes, int n_in,
                              void* d_out, int out_size) {
    const float* tok  = (const float*)d_in[0];
    const float* asp  = (const float*)d_in[1];
    const float* W    = (const float*)d_in[2];
    const float* bias = (const float*)d_in[3];
    const float* v    = (const float*)d_in[4];
    float* out = (float*)d_out;

    cudaFuncSetAttribute(gemm_score_mma, cudaFuncAttributeMaxDynamicSharedMemorySize,
                         SMEM_TOTAL);

    prep_kernel<<<5184, 256>>>((const float4*)tok, W, asp, bias);
    gemm_score_mma<<<(Bd * Sd) / BM, 256, SMEM_TOTAL>>>(v);
    softmax_kernel<<<Bd, 256>>>();
    scale_kernel<<<8192, 256>>>(tok, out, (Bd * Sd * Hd) / 4);
}

// round 8
// speedup vs baseline: 1.5625x; 1.4073x over previous
#include <cuda_runtime.h>
#include <cuda_bf16.h>
#include <stdint.h>
#include <math.h>

#define Hd 1024
#define Sd 2048
#define Bd 16
#define Ad 8
#define BS (Bd * Sd)          // 32768 rows

#define NCTA 296              // 148 SMs x 2
#define NUNIT 2048            // 256 m-tiles x 8 n-tiles
#define BM 128
#define BN 128
#define BKg 32
#define STG 4
#define LDT 80                          // padded row pitch bytes
#define A_SZ (BM * LDT)                 // 10240
#define STAGE_BYTES (2 * A_SZ)          // 20480
#define SMEM_TOTAL (STG * STAGE_BYTES)  // 81920 (x2 CTAs = 164KB/SM)

// ---------------------------------------------------------------------------
__device__ __nv_bfloat16 g_Xbf[(size_t)BS * Hd];       // 64 MB
__device__ __nv_bfloat16 g_Wt[(size_t)Hd * Hd];        // W1^T: [N][K]
__device__ float g_cvec[Bd * Hd];
__device__ float g_part[16 * BS];                      // 2 MB partial scores
__device__ float g_weights[Bd * Sd];

// ---------------------------------------------------------------------------
__device__ __forceinline__ uint32_t smem_u32(const void* p) {
    uint32_t a;
    asm("{ .reg .u64 t; cvta.to.shared.u64 t, %1; cvt.u32.u64 %0, t; }" : "=r"(a) : "l"(p));
    return a;
}
__device__ __forceinline__ void cpa16(uint32_t dst, const void* src) {
    asm volatile("cp.async.cg.shared.global [%0], [%1], 16;" :: "r"(dst), "l"(src));
}
__device__ __forceinline__ void cpa_commit() {
    asm volatile("cp.async.commit_group;" ::: "memory");
}
#define CPA_WAIT2() asm volatile("cp.async.wait_group 2;" ::: "memory")
#define LDSM4(r, addr)                                                        \
    asm volatile("ldmatrix.sync.aligned.m8n8.x4.shared.b16 {%0,%1,%2,%3}, [%4];" \
        : "=r"((r)[0]), "=r"((r)[1]), "=r"((r)[2]), "=r"((r)[3]) : "r"(addr))
__device__ __forceinline__ void mma16816(float* d, const uint32_t* a,
                                         uint32_t b0, uint32_t b1) {
    asm volatile(
        "mma.sync.aligned.m16n8k16.row.col.f32.bf16.bf16.f32 "
        "{%0,%1,%2,%3}, {%4,%5,%6,%7}, {%8,%9}, {%0,%1,%2,%3};"
        : "+f"(d[0]), "+f"(d[1]), "+f"(d[2]), "+f"(d[3])
        : "r"(a[0]), "r"(a[1]), "r"(a[2]), "r"(a[3]), "r"(b0), "r"(b1));
}
__device__ __forceinline__ float fast_tanh(float x) {
    float y;
    asm("tanh.approx.f32 %0, %1;" : "=f"(y) : "f"(x));
    return y;
}

// ---------------------------------------------------------------------------
// Fused prep: [0,4096) convert X; [4096,5120) transpose W1; [5120,5184) cvec.
// ---------------------------------------------------------------------------
__global__ void prep_kernel(const float4* __restrict__ X4,
                            const float* __restrict__ W,
                            const float* __restrict__ aspect,
                            const float* __restrict__ bias) {
    int bi = blockIdx.x, tid = threadIdx.x;
    if (bi < 4096) {
        int n4 = BS * Hd / 4;
        for (int i = bi * 256 + tid; i < n4; i += 4096 * 256) {
            float4 v = X4[i];
            __nv_bfloat162 lo = __floats2bfloat162_rn(v.x, v.y);
            __nv_bfloat162 hi = __floats2bfloat162_rn(v.z, v.w);
            uint2 pk;
            pk.x = *reinterpret_cast<uint32_t*>(&lo);
            pk.y = *reinterpret_cast<uint32_t*>(&hi);
            reinterpret_cast<uint2*>(g_Xbf)[i] = pk;
        }
    } else if (bi < 5120) {
        __shared__ float t[32][33];
        int q = bi - 4096;
        int n0 = (q & 31) * 32, k0 = (q >> 5) * 32;
        int tx = tid & 31, ty = tid >> 5;            // 32 x 8
        #pragma unroll
        for (int i = 0; i < 32; i += 8)
            t[ty + i][tx] = W[(size_t)(k0 + ty + i) * Hd + n0 + tx];
        __syncthreads();
        #pragma unroll
        for (int i = 0; i < 32; i += 8)
            g_Wt[(size_t)(n0 + ty + i) * Hd + k0 + tx] = __float2bfloat16(t[tx][ty + i]);
    } else {
        __shared__ float asp[Hd];
        int q = bi - 5120;
        int b = q & 15, hb = q >> 4;
        for (int k = tid; k < Hd; k += 256) {
            float s = 0.f;
            #pragma unroll
            for (int a = 0; a < Ad; ++a)
                s += aspect[(size_t)(b * Ad + a) * Hd + k];
            asp[k] = s * (1.0f / Ad);
        }
        __syncthreads();
        int h = hb * 256 + tid;
        float acc = bias[h];
        const float* Wp = W + (size_t)Hd * Hd + h;
        #pragma unroll 8
        for (int k = 0; k < Hd; ++k)
            acc = fmaf(asp[k], Wp[(size_t)k * Hd], acc);
        g_cvec[b * Hd + h] = acc;
    }
}

// ---------------------------------------------------------------------------
// Persistent fused GEMM + tanh + v-dot -> g_part.
// 296 CTAs; unit u = (mt, nt): 128 rows x 128 cols x K=1024.
// 8 warps, warp grid 4(M) x 2(N), warp tile 32x64; R5 4-stage pipeline.
// ---------------------------------------------------------------------------
__global__ void __launch_bounds__(256, 2)
gemm_score_mma(const float* __restrict__ v) {
    extern __shared__ char smem[];
    uint32_t sb = smem_u32(smem);

    int tid = threadIdx.x, lane = tid & 31, wid = tid >> 5;
    int warpM = wid & 3, warpN = wid >> 2;

    // ldmatrix per-thread offsets (within a stage)
    uint32_t aoff[2], boff[4];
    #pragma unroll
    for (int mt = 0; mt < 2; ++mt) {
        int r = warpM * 32 + mt * 16 + ((lane >> 3) & 1) * 8 + (lane & 7);
        aoff[mt] = r * LDT + (lane >> 4) * 16;
    }
    #pragma unroll
    for (int jp = 0; jp < 4; ++jp) {
        int n = warpN * 64 + (jp * 2 + (lane >> 4)) * 8 + (lane & 7);
        boff[jp] = A_SZ + n * LDT + ((lane >> 3) & 1) * 16;
    }

    // cp.async mapping: per stage, A/B each 128 rows x 64B; 2+2 chunks/thread
    int lr  = tid >> 2;            // rows 0..63 (and +64)
    int lc  = (tid & 3) * 16;
    int lck = (tid & 3) * 8;

    for (int u = blockIdx.x; u < NUNIT; u += NCTA) {
        int mt = u >> 3, nt = u & 7;
        int m0 = mt * BM;
        int b  = mt >> 4;
        const __nv_bfloat16* Ag = g_Xbf + (size_t)m0 * Hd;
        const __nv_bfloat16* Bg = g_Wt + (size_t)(nt * BN) * Hd;

        float acc[2][8][4];
        #pragma unroll
        for (int mq = 0; mq < 2; ++mq)
            #pragma unroll
            for (int j = 0; j < 8; ++j)
                #pragma unroll
                for (int e = 0; e < 4; ++e) acc[mq][j][e] = 0.f;

        // prologue: stages 0,1,2
        #pragma unroll
        for (int q = 0; q < STG - 1; ++q) {
            int k0 = q * BKg;
            uint32_t base = sb + q * STAGE_BYTES;
            cpa16(base + lr * LDT + lc,            Ag + (size_t)lr * Hd + k0 + lck);
            cpa16(base + (lr + 64) * LDT + lc,     Ag + (size_t)(lr + 64) * Hd + k0 + lck);
            cpa16(base + A_SZ + lr * LDT + lc,        Bg + (size_t)lr * Hd + k0 + lck);
            cpa16(base + A_SZ + (lr + 64) * LDT + lc, Bg + (size_t)(lr + 64) * Hd + k0 + lck);
            cpa_commit();
        }

        for (int g = 0; g < 32; ++g) {
            CPA_WAIT2();
            __syncthreads();
            int q = g + STG - 1;
            if (q < 32) {
                int k0 = q * BKg;
                uint32_t base = sb + (q & 3) * STAGE_BYTES;
                cpa16(base + lr * LDT + lc,            Ag + (size_t)lr * Hd + k0 + lck);
                cpa16(base + (lr + 64) * LDT + lc,     Ag + (size_t)(lr + 64) * Hd + k0 + lck);
                cpa16(base + A_SZ + lr * LDT + lc,        Bg + (size_t)lr * Hd + k0 + lck);
                cpa16(base + A_SZ + (lr + 64) * LDT + lc, Bg + (size_t)(lr + 64) * Hd + k0 + lck);
            }
            cpa_commit();     // unconditional: exact wait accounting at tail

            uint32_t ab = sb + (g & 3) * STAGE_BYTES;

            uint32_t a0[2][4], b0[4][4], a1[2][4], b1[4][4];
            LDSM4(a0[0], ab + aoff[0]);
            LDSM4(a0[1], ab + aoff[1]);
            #pragma unroll
            for (int jp = 0; jp < 4; ++jp) LDSM4(b0[jp], ab + boff[jp]);
            LDSM4(a1[0], ab + aoff[0] + 32);
            LDSM4(a1[1], ab + aoff[1] + 32);

            #pragma unroll
            for (int mq = 0; mq < 2; ++mq)
                #pragma unroll
                for (int j = 0; j < 8; ++j)
                    mma16816(acc[mq][j], a0[mq], b0[j >> 1][(j & 1) * 2],
                             b0[j >> 1][(j & 1) * 2 + 1]);

            #pragma unroll
            for (int jp = 0; jp < 4; ++jp) LDSM4(b1[jp], ab + boff[jp] + 32);

            #pragma unroll
            for (int mq = 0; mq < 2; ++mq)
                #pragma unroll
                for (int j = 0; j < 8; ++j)
                    mma16816(acc[mq][j], a1[mq], b1[j >> 1][(j & 1) * 2],
                             b1[j >> 1][(j & 1) * 2 + 1]);
        }

        // epilogue: tanh + v-dot over this unit's 128 cols
        int nb = nt * BN + warpN * 64 + (lane & 3) * 2;
        float vv[16], cv[16];
        #pragma unroll
        for (int j = 0; j < 8; ++j)
            #pragma unroll
            for (int h = 0; h < 2; ++h) {
                int n = nb + j * 8 + h;
                vv[j * 2 + h] = v[n];
                cv[j * 2 + h] = g_cvec[b * Hd + n];
            }

        float p[4] = {0.f, 0.f, 0.f, 0.f};
        #pragma unroll
        for (int mq = 0; mq < 2; ++mq)
            #pragma unroll
            for (int j = 0; j < 8; ++j)
                #pragma unroll
                for (int e = 0; e < 4; ++e) {
                    int h = e & 1, rh = e >> 1;
                    float x = acc[mq][j][e] + cv[j * 2 + h];
                    p[mq * 2 + rh] += vv[j * 2 + h] * fast_tanh(x);
                }

        #pragma unroll
        for (int i = 0; i < 4; ++i) {
            p[i] += __shfl_xor_sync(0xFFFFFFFFu, p[i], 1);
            p[i] += __shfl_xor_sync(0xFFFFFFFFu, p[i], 2);
        }
        if ((lane & 3) == 0) {
            int part = nt * 2 + warpN;
            #pragma unroll
            for (int mq = 0; mq < 2; ++mq)
                #pragma unroll
                for (int rh = 0; rh < 2; ++rh) {
                    int row = warpM * 32 + mq * 16 + (lane >> 2) + rh * 8;
                    g_part[part * BS + m0 + row] = p[mq * 2 + rh];
                }
        }
        // no extra barrier needed: next prologue writes stages 0-2, whose last
        // readers passed the g=29..31 barriers already.
    }
}

// ---------------------------------------------------------------------------
// softmax over S per batch; sums the 16 partials per row first.
// ---------------------------------------------------------------------------
__global__ void softmax_kernel() {
    int b = blockIdx.x, tid = threadIdx.x;
    __shared__ float red[256];
    __shared__ float sc[Sd];

    for (int s = tid; s < Sd; s += 256) {
        int row = b * Sd + s;
        float t = 0.f;
        #pragma unroll
        for (int j = 0; j < 16; ++j)
            t += g_part[j * BS + row];
        sc[s] = t;
    }
    __syncthreads();

    float m = -1e30f;
    for (int s = tid; s < Sd; s += 256) m = fmaxf(m, sc[s]);
    red[tid] = m;
    __syncthreads();
    for (int o = 128; o > 0; o >>= 1) {
        if (tid < o) red[tid] = fmaxf(red[tid], red[tid + o]);
        __syncthreads();
    }
    float mx = red[0];
    __syncthreads();
    float sum = 0.f;
    for (int s = tid; s < Sd; s += 256) {
        float e = expf(sc[s] - mx);
        g_weights[b * Sd + s] = e;
        sum += e;
    }
    red[tid] = sum;
    __syncthreads();
    for (int o = 128; o > 0; o >>= 1) {
        if (tid < o) red[tid] += red[tid + o];
        __syncthreads();
    }
    float inv = 1.0f / red[0];
    for (int s = tid; s < Sd; s += 256)
        g_weights[b * Sd + s] *= inv;
}

__global__ void scale_kernel(const float* __restrict__ X, float* __restrict__ out,
                             int total4) {
    int idx = blockIdx.x * blockDim.x + threadIdx.x;
    int stride = gridDim.x * blockDim.x;
    for (int i = idx; i < total4; i += stride) {
        float w = 1.0f + g_weights[i >> 8];
        float4 t = ((const float4*)X)[i];
        t.x *= w; t.y *= w; t.z *= w; t.w *= w;
        ((float4*)out)[i] = t;
    }
}

// ---------------------------------------------------------------------------
extern "C" void kernel_launch(void* const* d_in, const int* in_sizes, int n_in,
                              void* d_out, int out_size) {
    const float* tok  = (const float*)d_in[0];
    const float* asp  = (const float*)d_in[1];
    const float* W    = (const float*)d_in[2];
    const float* bias = (const float*)d_in[3];
    const float* v    = (const float*)d_in[4];
    float* out = (float*)d_out;

    cudaFuncSetAttribute(gemm_score_mma, cudaFuncAttributeMaxDynamicSharedMemorySize,
                         SMEM_TOTAL);

    prep_kernel<<<5184, 256>>>((const float4*)tok, W, asp, bias);
    gemm_score_mma<<<NCTA, 256, SMEM_TOTAL>>>(v);
    softmax_kernel<<<Bd, 256>>>();
    scale_kernel<<<8192, 256>>>(tok, out, (Bd * Sd * Hd) / 4);
}